// round 1
// baseline (speedup 1.0000x reference)
#include <cuda_runtime.h>
#include <cuda_bf16.h>
#include <cstdint>
#include <cstddef>

// Problem constants
#define Bb   2
#define Ss   2048
#define Hh   2048
#define NHh  16
#define HDd  128
#define Pp   2048
#define Mm   (Bb * Ss)          // 4096 rows
#define H2   (Hh / 2)           // 1024
#define QKW  (2 * Pp)           // 4096 (qk row width)
#define EPSc 1e-6f

// ---------------- scratch (static device globals; no allocation) ----------------
__device__ float g_v[(size_t)Mm * Pp];        // 32 MB
__device__ float g_xprev[(size_t)Mm * Hh];    // 32 MB
__device__ float g_y1[(size_t)Mm * H2];       // 16 MB
__device__ float g_y1prev[(size_t)Mm * H2];   // 16 MB
__device__ float g_lfout[(size_t)Mm * Hh];    // 32 MB  (y2, then lf_out in-place)
__device__ float g_qk[(size_t)Mm * QKW];      // 64 MB
__device__ float g_attn[(size_t)Mm * Pp];     // 32 MB
__device__ float g_w1a[(size_t)H2 * Hh];      // 8 MB
__device__ float g_w1b[(size_t)H2 * Hh];      // 8 MB
__device__ float g_w2a[(size_t)Hh * H2];      // 8 MB
__device__ float g_w2b[(size_t)Hh * H2];      // 8 MB

// ---------------- deinterleave conv weights: a[i]=in[2i], b[i]=in[2i+1] ----------------
__global__ void deint_kernel(const float* __restrict__ in, float* __restrict__ a,
                             float* __restrict__ b, int n)
{
    int i = blockIdx.x * 256 + threadIdx.x;
    if (i < n) {
        a[i] = in[2 * i];
        b[i] = in[2 * i + 1];
    }
}

// ---------------- shift rows by one seq step (row 0 of each batch <- cache) ----------------
__global__ void shift_kernel(const float* __restrict__ x, const float* __restrict__ cache,
                             float* __restrict__ out, int width)
{
    int m = blockIdx.x;
    int s = m % Ss;
    int b = m / Ss;
    const float* src = (s == 0) ? (cache + (size_t)b * width)
                                : (x + (size_t)(m - 1) * width);
    float* dst = out + (size_t)m * width;
    for (int i = threadIdx.x; i < width; i += 256) dst[i] = src[i];
}

// ---------------- SGEMM (NT): C[M,N] = A[M,K] * W[N,K]^T (+bias)(+C) ----------------
// 128x128 block tile, 8x8 per thread, K-tile 8, 256 threads. All dims % 128 == 0, K % 8 == 0.
__global__ __launch_bounds__(256) void gemm_nt_kernel(
    const float* __restrict__ A, const float* __restrict__ W, float* __restrict__ C,
    int N, int K, const float* __restrict__ bias, int accFlag)
{
    __shared__ float As[8][128];
    __shared__ float Bs[8][128];

    const int bm  = blockIdx.y * 128;
    const int bn  = blockIdx.x * 128;
    const int tid = threadIdx.x;
    const int lrow = tid >> 1;             // 0..127
    const int lcol = (tid & 1) << 2;       // 0 or 4
    const int ty = tid >> 4;               // 0..15
    const int tx = tid & 15;               // 0..15

    float acc[8][8];
#pragma unroll
    for (int i = 0; i < 8; i++)
#pragma unroll
        for (int j = 0; j < 8; j++) acc[i][j] = 0.f;

    const float* Aptr = A + (size_t)(bm + lrow) * K + lcol;
    const float* Wptr = W + (size_t)(bn + lrow) * K + lcol;

    for (int k0 = 0; k0 < K; k0 += 8) {
        float4 a4 = *(const float4*)(Aptr + k0);
        float4 b4 = *(const float4*)(Wptr + k0);
        __syncthreads();
        As[lcol + 0][lrow] = a4.x; As[lcol + 1][lrow] = a4.y;
        As[lcol + 2][lrow] = a4.z; As[lcol + 3][lrow] = a4.w;
        Bs[lcol + 0][lrow] = b4.x; Bs[lcol + 1][lrow] = b4.y;
        Bs[lcol + 2][lrow] = b4.z; Bs[lcol + 3][lrow] = b4.w;
        __syncthreads();
#pragma unroll
        for (int kk = 0; kk < 8; kk++) {
            float4 a0 = *(const float4*)&As[kk][ty * 8];
            float4 a1 = *(const float4*)&As[kk][ty * 8 + 4];
            float4 b0 = *(const float4*)&Bs[kk][tx * 8];
            float4 b1 = *(const float4*)&Bs[kk][tx * 8 + 4];
            float ar[8] = {a0.x, a0.y, a0.z, a0.w, a1.x, a1.y, a1.z, a1.w};
            float br[8] = {b0.x, b0.y, b0.z, b0.w, b1.x, b1.y, b1.z, b1.w};
#pragma unroll
            for (int i = 0; i < 8; i++)
#pragma unroll
                for (int j = 0; j < 8; j++)
                    acc[i][j] = fmaf(ar[i], br[j], acc[i][j]);
        }
    }

#pragma unroll
    for (int i = 0; i < 8; i++) {
        float* crow = C + (size_t)(bm + ty * 8 + i) * N + bn + tx * 8;
#pragma unroll
        for (int j = 0; j < 8; j++) {
            float v = acc[i][j];
            if (bias) v += bias[bn + tx * 8 + j];
            if (accFlag) v += crow[j];
            crow[j] = v;
        }
    }
}

// ---------------- residual add + RMSNorm (in-place into y2 buffer) ----------------
__global__ __launch_bounds__(256) void rmsnorm_kernel(
    float* __restrict__ y2, const float* __restrict__ x, const float* __restrict__ w)
{
    int m = blockIdx.x;
    float* yrow = y2 + (size_t)m * Hh;
    const float* xrow = x + (size_t)m * Hh;

    float ss = 0.f;
    for (int i = threadIdx.x; i < Hh; i += 256) {
        float t = yrow[i] + xrow[i];
        ss += t * t;
    }
#pragma unroll
    for (int off = 16; off > 0; off >>= 1)
        ss += __shfl_xor_sync(0xffffffffu, ss, off);

    __shared__ float red[9];
    int lane = threadIdx.x & 31, wid = threadIdx.x >> 5;
    if (lane == 0) red[wid] = ss;
    __syncthreads();
    if (threadIdx.x == 0) {
        float tot = 0.f;
        for (int i = 0; i < 8; i++) tot += red[i];
        red[8] = rsqrtf(tot / (float)Hh + EPSc);
    }
    __syncthreads();
    float inv = red[8];
    for (int i = threadIdx.x; i < Hh; i += 256) {
        float t = yrow[i] + xrow[i];
        yrow[i] = t * w[i] * inv;
    }
}

// ---------------- RoPE in place on qk buffer ----------------
__global__ __launch_bounds__(128) void rope_kernel(
    float* __restrict__ qkbuf, const float* __restrict__ freqs,
    const int* __restrict__ positions)
{
    int mh = blockIdx.x;                  // m*NH + h
    int m = mh / NHh, h = mh % NHh;
    int pos = positions[m];
    int t = threadIdx.x;                  // 0..127
    int isK = t >> 6;                     // 0 = q half, 1 = k half
    int d = t & 63;

    size_t base = (size_t)m * QKW + (size_t)h * 256 + (size_t)isK * 128;
    float f1 = freqs[(size_t)pos * HDd + d];
    float f2 = freqs[(size_t)pos * HDd + d + 64];
    float c1 = cosf(f1), s1 = sinf(f1);
    float c2 = cosf(f2), s2 = sinf(f2);
    float x1 = qkbuf[base + d];
    float x2 = qkbuf[base + d + 64];
    qkbuf[base + d]      = x1 * c1 - x2 * s1;
    qkbuf[base + d + 64] = x2 * c2 + x1 * s2;
}

// ---------------- causal flash attention ----------------
// Block: 256 threads = 64 queries x 4 dim-parts (interleaved dims d = i*4 + part).
// K tile = 32 keys staged in smem. q,k read from g_qk (post-RoPE), v from g_v.
#define TQ 64
#define TK 32
__global__ __launch_bounds__(256) void flash_kernel(
    const float* __restrict__ qkbuf, const float* __restrict__ vbuf,
    float* __restrict__ attn)
{
    int qt = blockIdx.x;      // 0..31
    int h  = blockIdx.y;      // 0..15
    int b  = blockIdx.z;      // 0..1
    int q0 = qt * TQ;
    int tid = threadIdx.x;
    int g = tid >> 2;         // query within tile
    int part = tid & 3;

    __shared__ float Ks[TK][HDd];
    __shared__ float Vs[TK][HDd];

    int qi = q0 + g;
    size_t qbase = (size_t)(b * Ss + qi) * QKW + (size_t)h * 256;
    const float scale = 0.08838834764831845f;   // 1/sqrt(128)

    float qr[32], o[32];
#pragma unroll
    for (int i = 0; i < 32; i++) {
        qr[i] = qkbuf[qbase + i * 4 + part] * scale;
        o[i] = 0.f;
    }
    float mval = -1e30f, lval = 0.f;

    int kend = q0 + TQ;   // causal: keys < kend considered; diagonal masked per-pair
    for (int j0 = 0; j0 < kend; j0 += TK) {
        __syncthreads();
        for (int t = tid; t < TK * HDd / 4; t += 256) {
            int row = t >> 5;                // 32 float4 per row
            int c4 = (t & 31) << 2;
            size_t kb = (size_t)(b * Ss + j0 + row) * QKW + (size_t)h * 256 + 128 + c4;
            size_t vb = (size_t)(b * Ss + j0 + row) * Pp + (size_t)h * HDd + c4;
            *(float4*)&Ks[row][c4] = *(const float4*)(qkbuf + kb);
            *(float4*)&Vs[row][c4] = *(const float4*)(vbuf + vb);
        }
        __syncthreads();

#pragma unroll 1
        for (int j = 0; j < TK; j++) {
            int kpos = j0 + j;
            float s = 0.f;
#pragma unroll
            for (int i = 0; i < 32; i++) s = fmaf(qr[i], Ks[j][i * 4 + part], s);
            s += __shfl_xor_sync(0xffffffffu, s, 1);
            s += __shfl_xor_sync(0xffffffffu, s, 2);
            if (kpos > qi) s = -1e30f;

            float mnew = fmaxf(mval, s);
            float alpha = __expf(mval - mnew);
            float p = __expf(s - mnew);
            lval = lval * alpha + p;
            mval = mnew;
#pragma unroll
            for (int i = 0; i < 32; i++)
                o[i] = fmaf(o[i], alpha, p * Vs[j][i * 4 + part]);
        }
    }

    float inv = 1.f / lval;
    size_t ob = (size_t)(b * Ss + qi) * Pp + (size_t)h * HDd;
#pragma unroll
    for (int i = 0; i < 32; i++) attn[ob + i * 4 + part] = o[i] * inv;
}

// ---------------- tail outputs: lf1_new, lf2_new ----------------
__global__ void tails_kernel(const float* __restrict__ hs, const float* __restrict__ y1,
                             float* __restrict__ out)
{
    int i = blockIdx.x * 256 + threadIdx.x;
    size_t off1 = (size_t)Mm * Hh;                 // lf1_new: B*H floats
    size_t off2 = off1 + (size_t)Bb * Hh;          // lf2_new: B*H/2 floats
    if (i < Bb * Hh) {
        int b = i / Hh, hh = i % Hh;
        out[off1 + i] = hs[((size_t)b * Ss + (Ss - 1)) * Hh + hh];
    }
    if (i < Bb * H2) {
        int b = i / H2, oo = i % H2;
        out[off2 + i] = y1[((size_t)b * Ss + (Ss - 1)) * H2 + oo];
    }
}

// ---------------- launch ----------------
extern "C" void kernel_launch(void* const* d_in, const int* in_sizes, int n_in,
                              void* d_out, int out_size)
{
    (void)in_sizes; (void)n_in; (void)out_size;
    const float* hs      = (const float*)d_in[0];   // [B,S,H]
    const float* freqs   = (const float*)d_in[1];   // [MAXP,1,1,HD]
    const int*   pos     = (const int*)  d_in[2];   // [B*S]
    const float* Wqk     = (const float*)d_in[3];   // [2P,H]
    const float* Wv      = (const float*)d_in[4];   // [P,H]
    const float* Wo      = (const float*)d_in[5];   // [H,P]
    const float* conv1_w = (const float*)d_in[6];   // [H/2,H,2,1]
    const float* conv1_b = (const float*)d_in[7];   // [H/2]
    const float* conv2_w = (const float*)d_in[8];   // [H,H/2,2,1]
    const float* conv2_b = (const float*)d_in[9];   // [H]
    const float* ln_w    = (const float*)d_in[10];  // [H]
    const float* lf1c    = (const float*)d_in[11];  // [B,H,1,1]
    const float* lf2c    = (const float*)d_in[12];  // [B,H/2,1,1]
    float* out = (float*)d_out;

    float *v, *xprev, *y1, *y1prev, *lfout, *qk, *attn;
    float *w1a, *w1b, *w2a, *w2b;
    cudaGetSymbolAddress((void**)&v,      g_v);
    cudaGetSymbolAddress((void**)&xprev,  g_xprev);
    cudaGetSymbolAddress((void**)&y1,     g_y1);
    cudaGetSymbolAddress((void**)&y1prev, g_y1prev);
    cudaGetSymbolAddress((void**)&lfout,  g_lfout);
    cudaGetSymbolAddress((void**)&qk,     g_qk);
    cudaGetSymbolAddress((void**)&attn,   g_attn);
    cudaGetSymbolAddress((void**)&w1a,    g_w1a);
    cudaGetSymbolAddress((void**)&w1b,    g_w1b);
    cudaGetSymbolAddress((void**)&w2a,    g_w2a);
    cudaGetSymbolAddress((void**)&w2b,    g_w2b);

    // 1) deinterleave conv weights
    {
        int n1 = H2 * Hh;   // conv1: 1024*2048
        deint_kernel<<<(n1 + 255) / 256, 256>>>(conv1_w, w1a, w1b, n1);
        int n2 = Hh * H2;   // conv2: 2048*1024
        deint_kernel<<<(n2 + 255) / 256, 256>>>(conv2_w, w2a, w2b, n2);
    }

    // 2) shifted hidden (xprev)
    shift_kernel<<<Mm, 256>>>(hs, lf1c, xprev, Hh);

    // 3) v = hs @ Wv^T   [4096 x 2048], K=2048
    gemm_nt_kernel<<<dim3(Pp / 128, Mm / 128), 256>>>(hs, Wv, v, Pp, Hh, nullptr, 0);

    // 4) y1 = xprev @ w1a^T + hs @ w1b^T + b1   [4096 x 1024], K=2048
    gemm_nt_kernel<<<dim3(H2 / 128, Mm / 128), 256>>>(xprev, w1a, y1, H2, Hh, nullptr, 0);
    gemm_nt_kernel<<<dim3(H2 / 128, Mm / 128), 256>>>(hs,    w1b, y1, H2, Hh, conv1_b, 1);

    // 5) shifted y1 (y1prev)
    shift_kernel<<<Mm, 256>>>(y1, lf2c, y1prev, H2);

    // 6) y2 = y1prev @ w2a^T + y1 @ w2b^T + b2   [4096 x 2048], K=1024  -> lfout buffer
    gemm_nt_kernel<<<dim3(Hh / 128, Mm / 128), 256>>>(y1prev, w2a, lfout, Hh, H2, nullptr, 0);
    gemm_nt_kernel<<<dim3(Hh / 128, Mm / 128), 256>>>(y1,     w2b, lfout, Hh, H2, conv2_b, 1);

    // 7) lf_out = rmsnorm(y2 + hs) * ln_w  (in place)
    rmsnorm_kernel<<<Mm, 256>>>(lfout, hs, ln_w);

    // 8) qk = lf_out @ Wqk^T   [4096 x 4096], K=2048
    gemm_nt_kernel<<<dim3(QKW / 128, Mm / 128), 256>>>(lfout, Wqk, qk, QKW, Hh, nullptr, 0);

    // 9) RoPE in place
    rope_kernel<<<Mm * NHh, 128>>>(qk, freqs, pos);

    // 10) causal flash attention -> attn
    flash_kernel<<<dim3(Ss / TQ, NHh, Bb), 256>>>(qk, v, attn);

    // 11) output = attn @ Wo^T   [4096 x 2048], K=2048  -> d_out
    gemm_nt_kernel<<<dim3(Hh / 128, Mm / 128), 256>>>(attn, Wo, out, Hh, Pp, nullptr, 0);

    // 12) tails
    tails_kernel<<<(Bb * Hh + 255) / 256, 256>>>(hs, y1, out);
}

// round 2
// speedup vs baseline: 1.8233x; 1.8233x over previous
#include <cuda_runtime.h>
#include <cuda_bf16.h>
#include <cstdint>
#include <cstddef>

// Problem constants
#define Bb   2
#define Ss   2048
#define Hh   2048
#define NHh  16
#define HDd  128
#define Pp   2048
#define Mm   (Bb * Ss)          // 4096 rows
#define H2   (Hh / 2)           // 1024
#define QKW  (2 * Pp)           // 4096 (qk row width)
#define EPSc 1e-6f

// ---------------- scratch (static device globals; no allocation) ----------------
__device__ float g_v[(size_t)Mm * Pp];
__device__ float g_xprev[(size_t)Mm * Hh];
__device__ float g_y1[(size_t)Mm * H2];
__device__ float g_y1prev[(size_t)Mm * H2];
__device__ float g_lfout[(size_t)Mm * Hh];
__device__ float g_qk[(size_t)Mm * QKW];
__device__ float g_attn[(size_t)Mm * Pp];
__device__ float g_w1a[(size_t)H2 * Hh];
__device__ float g_w1b[(size_t)H2 * Hh];
__device__ float g_w2a[(size_t)Hh * H2];
__device__ float g_w2b[(size_t)Hh * H2];

// ---------------- helpers ----------------
__device__ __forceinline__ uint32_t f2tf(float x) {
    uint32_t r;
    asm("cvt.rna.tf32.f32 %0, %1;" : "=r"(r) : "f"(x));
    return r;
}

__device__ __forceinline__ void mma_tf32(float* d, const uint32_t* a, const uint32_t* b) {
    asm volatile(
        "mma.sync.aligned.m16n8k8.row.col.f32.tf32.tf32.f32 "
        "{%0,%1,%2,%3},{%4,%5,%6,%7},{%8,%9},{%0,%1,%2,%3};"
        : "+f"(d[0]), "+f"(d[1]), "+f"(d[2]), "+f"(d[3])
        : "r"(a[0]), "r"(a[1]), "r"(a[2]), "r"(a[3]), "r"(b[0]), "r"(b[1]));
}

__device__ __forceinline__ void cp16(void* smem, const void* g) {
    uint32_t s = (uint32_t)__cvta_generic_to_shared(smem);
    asm volatile("cp.async.ca.shared.global [%0], [%1], 16;" :: "r"(s), "l"(g));
}

// ---------------- deinterleave conv weights ----------------
__global__ void deint_kernel(const float* __restrict__ in, float* __restrict__ a,
                             float* __restrict__ b, int n)
{
    int i = blockIdx.x * 256 + threadIdx.x;
    if (i < n) {
        a[i] = in[2 * i];
        b[i] = in[2 * i + 1];
    }
}

// ---------------- shift rows by one seq step ----------------
__global__ void shift_kernel(const float* __restrict__ x, const float* __restrict__ cache,
                             float* __restrict__ out, int width)
{
    int m = blockIdx.x;
    int s = m % Ss;
    int b = m / Ss;
    const float* src = (s == 0) ? (cache + (size_t)b * width)
                                : (x + (size_t)(m - 1) * width);
    float* dst = out + (size_t)m * width;
    for (int i = threadIdx.x; i < width; i += 256) dst[i] = src[i];
}

// ---------------- TF32 tensor-core GEMM (NT): C[M,N] = A[M,K] * W[N,K]^T (+bias)(+C) ----------------
// 128x128 block tile, BK=16, 256 threads = 8 warps (2x4), warp tile 64x32 via m16n8k8.
// All dims % 128 == 0, K % 16 == 0.
#define BMg 128
#define BNg 128
#define BKg 16
#define PADg 20   // floats per smem row (keeps 16B align, conflict-free frags)

__global__ __launch_bounds__(256) void gemm_tf32_kernel(
    const float* __restrict__ A, const float* __restrict__ W, float* __restrict__ C,
    int N, int K, const float* __restrict__ bias, int accFlag)
{
    __shared__ float As[2][BMg * PADg];
    __shared__ float Bs[2][BNg * PADg];

    const int tid = threadIdx.x;
    const int lane = tid & 31;
    const int warp = tid >> 5;
    const int wm = warp >> 2;          // 0..1
    const int wn = warp & 3;           // 0..3
    const int bm = blockIdx.y * BMg;
    const int bn = blockIdx.x * BNg;
    const int mBase = wm * 64;
    const int nBase = wn * 32;

    float acc[4][4][4];
#pragma unroll
    for (int mi = 0; mi < 4; mi++)
#pragma unroll
        for (int ni = 0; ni < 4; ni++)
#pragma unroll
            for (int e = 0; e < 4; e++) acc[mi][ni][e] = 0.f;

    const int nk = K / BKg;

    // chunk c in [0,512): row = c>>2, col floats = (c&3)*4 ; thread does c=tid, tid+256
    auto load_tiles = [&](int buf, int k0) {
#pragma unroll
        for (int c = tid; c < 512; c += 256) {
            int row = c >> 2;
            int colf = (c & 3) << 2;
            cp16(&As[buf][row * PADg + colf], A + (size_t)(bm + row) * K + k0 + colf);
            cp16(&Bs[buf][row * PADg + colf], W + (size_t)(bn + row) * K + k0 + colf);
        }
        asm volatile("cp.async.commit_group;");
    };

    load_tiles(0, 0);

    const int row4 = lane >> 2;   // 0..7
    const int col4 = lane & 3;    // 0..3

    for (int kt = 0; kt < nk; kt++) {
        int buf = kt & 1;
        if (kt + 1 < nk) {
            load_tiles(buf ^ 1, (kt + 1) * BKg);
            asm volatile("cp.async.wait_group 1;");
        } else {
            asm volatile("cp.async.wait_group 0;");
        }
        __syncthreads();

        const float* as = &As[buf][0];
        const float* bs = &Bs[buf][0];
#pragma unroll
        for (int kk = 0; kk < BKg; kk += 8) {
            uint32_t af[4][4], bf[4][2];
#pragma unroll
            for (int mi = 0; mi < 4; mi++) {
                int m0 = mBase + mi * 16;
                af[mi][0] = f2tf(as[(m0 + row4) * PADg + kk + col4]);
                af[mi][1] = f2tf(as[(m0 + row4 + 8) * PADg + kk + col4]);
                af[mi][2] = f2tf(as[(m0 + row4) * PADg + kk + col4 + 4]);
                af[mi][3] = f2tf(as[(m0 + row4 + 8) * PADg + kk + col4 + 4]);
            }
#pragma unroll
            for (int ni = 0; ni < 4; ni++) {
                int n0 = nBase + ni * 8;
                bf[ni][0] = f2tf(bs[(n0 + row4) * PADg + kk + col4]);
                bf[ni][1] = f2tf(bs[(n0 + row4) * PADg + kk + col4 + 4]);
            }
#pragma unroll
            for (int mi = 0; mi < 4; mi++)
#pragma unroll
                for (int ni = 0; ni < 4; ni++)
                    mma_tf32(acc[mi][ni], af[mi], bf[ni]);
        }
        __syncthreads();
    }

    // epilogue: c0,c1 at (row4, 2*col4+{0,1}); c2,c3 at (row4+8, same)
#pragma unroll
    for (int mi = 0; mi < 4; mi++) {
        int r0 = bm + mBase + mi * 16 + row4;
#pragma unroll
        for (int ni = 0; ni < 4; ni++) {
            int cb = bn + nBase + ni * 8 + 2 * col4;
            float2 b2 = make_float2(0.f, 0.f);
            if (bias) { b2.x = bias[cb]; b2.y = bias[cb + 1]; }

            float* p0 = C + (size_t)r0 * N + cb;
            float* p1 = C + (size_t)(r0 + 8) * N + cb;
            float2 v0 = make_float2(acc[mi][ni][0] + b2.x, acc[mi][ni][1] + b2.y);
            float2 v1 = make_float2(acc[mi][ni][2] + b2.x, acc[mi][ni][3] + b2.y);
            if (accFlag) {
                float2 o0 = *(float2*)p0, o1 = *(float2*)p1;
                v0.x += o0.x; v0.y += o0.y;
                v1.x += o1.x; v1.y += o1.y;
            }
            *(float2*)p0 = v0;
            *(float2*)p1 = v1;
        }
    }
}

// ---------------- residual add + RMSNorm (in-place into y2 buffer) ----------------
__global__ __launch_bounds__(256) void rmsnorm_kernel(
    float* __restrict__ y2, const float* __restrict__ x, const float* __restrict__ w)
{
    int m = blockIdx.x;
    float* yrow = y2 + (size_t)m * Hh;
    const float* xrow = x + (size_t)m * Hh;

    float ss = 0.f;
    for (int i = threadIdx.x; i < Hh; i += 256) {
        float t = yrow[i] + xrow[i];
        ss += t * t;
    }
#pragma unroll
    for (int off = 16; off > 0; off >>= 1)
        ss += __shfl_xor_sync(0xffffffffu, ss, off);

    __shared__ float red[9];
    int lane = threadIdx.x & 31, wid = threadIdx.x >> 5;
    if (lane == 0) red[wid] = ss;
    __syncthreads();
    if (threadIdx.x == 0) {
        float tot = 0.f;
        for (int i = 0; i < 8; i++) tot += red[i];
        red[8] = rsqrtf(tot / (float)Hh + EPSc);
    }
    __syncthreads();
    float inv = red[8];
    for (int i = threadIdx.x; i < Hh; i += 256) {
        float t = yrow[i] + xrow[i];
        yrow[i] = t * w[i] * inv;
    }
}

// ---------------- RoPE in place on qk buffer ----------------
__global__ __launch_bounds__(128) void rope_kernel(
    float* __restrict__ qkbuf, const float* __restrict__ freqs,
    const int* __restrict__ positions)
{
    int mh = blockIdx.x;
    int m = mh / NHh, h = mh % NHh;
    int pos = positions[m];
    int t = threadIdx.x;
    int isK = t >> 6;
    int d = t & 63;

    size_t base = (size_t)m * QKW + (size_t)h * 256 + (size_t)isK * 128;
    float f1 = freqs[(size_t)pos * HDd + d];
    float f2 = freqs[(size_t)pos * HDd + d + 64];
    float c1 = cosf(f1), s1 = sinf(f1);
    float c2 = cosf(f2), s2 = sinf(f2);
    float x1 = qkbuf[base + d];
    float x2 = qkbuf[base + d + 64];
    qkbuf[base + d]      = x1 * c1 - x2 * s1;
    qkbuf[base + d + 64] = x2 * c2 + x1 * s2;
}

// ---------------- causal flash attention ----------------
#define TQ 64
#define TK 32
__global__ __launch_bounds__(256) void flash_kernel(
    const float* __restrict__ qkbuf, const float* __restrict__ vbuf,
    float* __restrict__ attn)
{
    int qt = blockIdx.x;
    int h  = blockIdx.y;
    int b  = blockIdx.z;
    int q0 = qt * TQ;
    int tid = threadIdx.x;
    int g = tid >> 2;
    int part = tid & 3;

    __shared__ float Ks[TK][HDd];
    __shared__ float Vs[TK][HDd];

    int qi = q0 + g;
    size_t qbase = (size_t)(b * Ss + qi) * QKW + (size_t)h * 256;
    const float scale = 0.08838834764831845f;

    float qr[32], o[32];
#pragma unroll
    for (int i = 0; i < 32; i++) {
        qr[i] = qkbuf[qbase + i * 4 + part] * scale;
        o[i] = 0.f;
    }
    float mval = -1e30f, lval = 0.f;

    int kend = q0 + TQ;
    for (int j0 = 0; j0 < kend; j0 += TK) {
        __syncthreads();
        for (int t = tid; t < TK * HDd / 4; t += 256) {
            int row = t >> 5;
            int c4 = (t & 31) << 2;
            size_t kb = (size_t)(b * Ss + j0 + row) * QKW + (size_t)h * 256 + 128 + c4;
            size_t vb = (size_t)(b * Ss + j0 + row) * Pp + (size_t)h * HDd + c4;
            *(float4*)&Ks[row][c4] = *(const float4*)(qkbuf + kb);
            *(float4*)&Vs[row][c4] = *(const float4*)(vbuf + vb);
        }
        __syncthreads();

#pragma unroll 1
        for (int j = 0; j < TK; j++) {
            int kpos = j0 + j;
            float s = 0.f;
#pragma unroll
            for (int i = 0; i < 32; i++) s = fmaf(qr[i], Ks[j][i * 4 + part], s);
            s += __shfl_xor_sync(0xffffffffu, s, 1);
            s += __shfl_xor_sync(0xffffffffu, s, 2);
            if (kpos > qi) s = -1e30f;

            float mnew = fmaxf(mval, s);
            float alpha = __expf(mval - mnew);
            float p = __expf(s - mnew);
            lval = lval * alpha + p;
            mval = mnew;
#pragma unroll
            for (int i = 0; i < 32; i++)
                o[i] = fmaf(o[i], alpha, p * Vs[j][i * 4 + part]);
        }
    }

    float inv = 1.f / lval;
    size_t ob = (size_t)(b * Ss + qi) * Pp + (size_t)h * HDd;
#pragma unroll
    for (int i = 0; i < 32; i++) attn[ob + i * 4 + part] = o[i] * inv;
}

// ---------------- tail outputs ----------------
__global__ void tails_kernel(const float* __restrict__ hs, const float* __restrict__ y1,
                             float* __restrict__ out)
{
    int i = blockIdx.x * 256 + threadIdx.x;
    size_t off1 = (size_t)Mm * Hh;
    size_t off2 = off1 + (size_t)Bb * Hh;
    if (i < Bb * Hh) {
        int b = i / Hh, hh = i % Hh;
        out[off1 + i] = hs[((size_t)b * Ss + (Ss - 1)) * Hh + hh];
    }
    if (i < Bb * H2) {
        int b = i / H2, oo = i % H2;
        out[off2 + i] = y1[((size_t)b * Ss + (Ss - 1)) * H2 + oo];
    }
}

// ---------------- launch ----------------
extern "C" void kernel_launch(void* const* d_in, const int* in_sizes, int n_in,
                              void* d_out, int out_size)
{
    (void)in_sizes; (void)n_in; (void)out_size;
    const float* hs      = (const float*)d_in[0];
    const float* freqs   = (const float*)d_in[1];
    const int*   pos     = (const int*)  d_in[2];
    const float* Wqk     = (const float*)d_in[3];
    const float* Wv      = (const float*)d_in[4];
    const float* Wo      = (const float*)d_in[5];
    const float* conv1_w = (const float*)d_in[6];
    const float* conv1_b = (const float*)d_in[7];
    const float* conv2_w = (const float*)d_in[8];
    const float* conv2_b = (const float*)d_in[9];
    const float* ln_w    = (const float*)d_in[10];
    const float* lf1c    = (const float*)d_in[11];
    const float* lf2c    = (const float*)d_in[12];
    float* out = (float*)d_out;

    float *v, *xprev, *y1, *y1prev, *lfout, *qk, *attn;
    float *w1a, *w1b, *w2a, *w2b;
    cudaGetSymbolAddress((void**)&v,      g_v);
    cudaGetSymbolAddress((void**)&xprev,  g_xprev);
    cudaGetSymbolAddress((void**)&y1,     g_y1);
    cudaGetSymbolAddress((void**)&y1prev, g_y1prev);
    cudaGetSymbolAddress((void**)&lfout,  g_lfout);
    cudaGetSymbolAddress((void**)&qk,     g_qk);
    cudaGetSymbolAddress((void**)&attn,   g_attn);
    cudaGetSymbolAddress((void**)&w1a,    g_w1a);
    cudaGetSymbolAddress((void**)&w1b,    g_w1b);
    cudaGetSymbolAddress((void**)&w2a,    g_w2a);
    cudaGetSymbolAddress((void**)&w2b,    g_w2b);

    // 1) deinterleave conv weights
    {
        int n1 = H2 * Hh;
        deint_kernel<<<(n1 + 255) / 256, 256>>>(conv1_w, w1a, w1b, n1);
        int n2 = Hh * H2;
        deint_kernel<<<(n2 + 255) / 256, 256>>>(conv2_w, w2a, w2b, n2);
    }

    // 2) shifted hidden
    shift_kernel<<<Mm, 256>>>(hs, lf1c, xprev, Hh);

    // 3) v = hs @ Wv^T
    gemm_tf32_kernel<<<dim3(Pp / BNg, Mm / BMg), 256>>>(hs, Wv, v, Pp, Hh, nullptr, 0);

    // 4) y1 = xprev @ w1a^T + hs @ w1b^T + b1
    gemm_tf32_kernel<<<dim3(H2 / BNg, Mm / BMg), 256>>>(xprev, w1a, y1, H2, Hh, nullptr, 0);
    gemm_tf32_kernel<<<dim3(H2 / BNg, Mm / BMg), 256>>>(hs,    w1b, y1, H2, Hh, conv1_b, 1);

    // 5) shifted y1
    shift_kernel<<<Mm, 256>>>(y1, lf2c, y1prev, H2);

    // 6) y2 = y1prev @ w2a^T + y1 @ w2b^T + b2
    gemm_tf32_kernel<<<dim3(Hh / BNg, Mm / BMg), 256>>>(y1prev, w2a, lfout, Hh, H2, nullptr, 0);
    gemm_tf32_kernel<<<dim3(Hh / BNg, Mm / BMg), 256>>>(y1,     w2b, lfout, Hh, H2, conv2_b, 1);

    // 7) lf_out = rmsnorm(y2 + hs) * ln_w
    rmsnorm_kernel<<<Mm, 256>>>(lfout, hs, ln_w);

    // 8) qk = lf_out @ Wqk^T
    gemm_tf32_kernel<<<dim3(QKW / BNg, Mm / BMg), 256>>>(lfout, Wqk, qk, QKW, Hh, nullptr, 0);

    // 9) RoPE in place
    rope_kernel<<<Mm * NHh, 128>>>(qk, freqs, pos);

    // 10) causal flash attention
    flash_kernel<<<dim3(Ss / TQ, NHh, Bb), 256>>>(qk, v, attn);

    // 11) output = attn @ Wo^T
    gemm_tf32_kernel<<<dim3(Hh / BNg, Mm / BMg), 256>>>(attn, Wo, out, Hh, Pp, nullptr, 0);

    // 12) tails
    tails_kernel<<<(Bb * Hh + 255) / 256, 256>>>(hs, y1, out);
}

// round 3
// speedup vs baseline: 1.8313x; 1.0044x over previous
#include <cuda_runtime.h>
#include <cuda_bf16.h>
#include <cstdint>
#include <cstddef>

// Problem constants
#define Bb   2
#define Ss   2048
#define Hh   2048
#define NHh  16
#define HDd  128
#define Pp   2048
#define Mm   (Bb * Ss)          // 4096 rows
#define H2   (Hh / 2)           // 1024
#define QKW  (2 * Pp)           // 4096 (qk row width)
#define EPSc 1e-6f

// ---------------- scratch (static device globals; no allocation) ----------------
__device__ float g_v[(size_t)Mm * Pp];
__device__ float g_xprev[(size_t)Mm * Hh];
__device__ float g_y1[(size_t)Mm * H2];
__device__ float g_y1prev[(size_t)Mm * H2];
__device__ float g_lfout[(size_t)Mm * Hh];
__device__ float g_qk[(size_t)Mm * QKW];
__device__ float g_attn[(size_t)Mm * Pp];
__device__ float g_w1a[(size_t)H2 * Hh];
__device__ float g_w1b[(size_t)H2 * Hh];
__device__ float g_w2a[(size_t)Hh * H2];
__device__ float g_w2b[(size_t)Hh * H2];

// ---------------- helpers ----------------
__device__ __forceinline__ uint32_t f2tf(float x) {
    uint32_t r;
    asm("cvt.rna.tf32.f32 %0, %1;" : "=r"(r) : "f"(x));
    return r;
}

__device__ __forceinline__ void mma_tf32(float* d, const uint32_t* a, const uint32_t* b) {
    asm volatile(
        "mma.sync.aligned.m16n8k8.row.col.f32.tf32.tf32.f32 "
        "{%0,%1,%2,%3},{%4,%5,%6,%7},{%8,%9},{%0,%1,%2,%3};"
        : "+f"(d[0]), "+f"(d[1]), "+f"(d[2]), "+f"(d[3])
        : "r"(a[0]), "r"(a[1]), "r"(a[2]), "r"(a[3]), "r"(b[0]), "r"(b[1]));
}

__device__ __forceinline__ void cp16(void* smem, const void* g) {
    uint32_t s = (uint32_t)__cvta_generic_to_shared(smem);
    asm volatile("cp.async.ca.shared.global [%0], [%1], 16;" :: "r"(s), "l"(g));
}

// ---------------- deinterleave conv weights ----------------
__global__ void deint_kernel(const float* __restrict__ in, float* __restrict__ a,
                             float* __restrict__ b, int n)
{
    int i = blockIdx.x * 256 + threadIdx.x;
    if (i < n) {
        a[i] = in[2 * i];
        b[i] = in[2 * i + 1];
    }
}

// ---------------- shift rows by one seq step ----------------
__global__ void shift_kernel(const float* __restrict__ x, const float* __restrict__ cache,
                             float* __restrict__ out, int width)
{
    int m = blockIdx.x;
    int s = m % Ss;
    int b = m / Ss;
    const float* src = (s == 0) ? (cache + (size_t)b * width)
                                : (x + (size_t)(m - 1) * width);
    float* dst = out + (size_t)m * width;
    for (int i = threadIdx.x; i < width; i += 256) dst[i] = src[i];
}

// ---------------- TF32 tensor-core GEMM (NT): C[M,N] = A[M,K] * W[N,K]^T (+bias)(+C) ----------------
// 128x128 block tile, BK=16, 256 threads = 8 warps (2x4), warp tile 64x32 via m16n8k8.
// All dims % 128 == 0, K % 16 == 0.
#define BMg 128
#define BNg 128
#define BKg 16
#define PADg 20   // floats per smem row (keeps 16B align, conflict-free frags)

__global__ __launch_bounds__(256) void gemm_tf32_kernel(
    const float* __restrict__ A, const float* __restrict__ W, float* __restrict__ C,
    int N, int K, const float* __restrict__ bias, int accFlag)
{
    __shared__ float As[2][BMg * PADg];
    __shared__ float Bs[2][BNg * PADg];

    const int tid = threadIdx.x;
    const int lane = tid & 31;
    const int warp = tid >> 5;
    const int wm = warp >> 2;          // 0..1
    const int wn = warp & 3;           // 0..3
    const int bm = blockIdx.y * BMg;
    const int bn = blockIdx.x * BNg;
    const int mBase = wm * 64;
    const int nBase = wn * 32;

    float acc[4][4][4];
#pragma unroll
    for (int mi = 0; mi < 4; mi++)
#pragma unroll
        for (int ni = 0; ni < 4; ni++)
#pragma unroll
            for (int e = 0; e < 4; e++) acc[mi][ni][e] = 0.f;

    const int nk = K / BKg;

    // chunk c in [0,512): row = c>>2, col floats = (c&3)*4 ; thread does c=tid, tid+256
    auto load_tiles = [&](int buf, int k0) {
#pragma unroll
        for (int c = tid; c < 512; c += 256) {
            int row = c >> 2;
            int colf = (c & 3) << 2;
            cp16(&As[buf][row * PADg + colf], A + (size_t)(bm + row) * K + k0 + colf);
            cp16(&Bs[buf][row * PADg + colf], W + (size_t)(bn + row) * K + k0 + colf);
        }
        asm volatile("cp.async.commit_group;");
    };

    load_tiles(0, 0);

    const int row4 = lane >> 2;   // 0..7
    const int col4 = lane & 3;    // 0..3

    for (int kt = 0; kt < nk; kt++) {
        int buf = kt & 1;
        if (kt + 1 < nk) {
            load_tiles(buf ^ 1, (kt + 1) * BKg);
            asm volatile("cp.async.wait_group 1;");
        } else {
            asm volatile("cp.async.wait_group 0;");
        }
        __syncthreads();

        const float* as = &As[buf][0];
        const float* bs = &Bs[buf][0];
#pragma unroll
        for (int kk = 0; kk < BKg; kk += 8) {
            uint32_t af[4][4], bf[4][2];
#pragma unroll
            for (int mi = 0; mi < 4; mi++) {
                int m0 = mBase + mi * 16;
                af[mi][0] = f2tf(as[(m0 + row4) * PADg + kk + col4]);
                af[mi][1] = f2tf(as[(m0 + row4 + 8) * PADg + kk + col4]);
                af[mi][2] = f2tf(as[(m0 + row4) * PADg + kk + col4 + 4]);
                af[mi][3] = f2tf(as[(m0 + row4 + 8) * PADg + kk + col4 + 4]);
            }
#pragma unroll
            for (int ni = 0; ni < 4; ni++) {
                int n0 = nBase + ni * 8;
                bf[ni][0] = f2tf(bs[(n0 + row4) * PADg + kk + col4]);
                bf[ni][1] = f2tf(bs[(n0 + row4) * PADg + kk + col4 + 4]);
            }
#pragma unroll
            for (int mi = 0; mi < 4; mi++)
#pragma unroll
                for (int ni = 0; ni < 4; ni++)
                    mma_tf32(acc[mi][ni], af[mi], bf[ni]);
        }
        __syncthreads();
    }

    // epilogue: c0,c1 at (row4, 2*col4+{0,1}); c2,c3 at (row4+8, same)
#pragma unroll
    for (int mi = 0; mi < 4; mi++) {
        int r0 = bm + mBase + mi * 16 + row4;
#pragma unroll
        for (int ni = 0; ni < 4; ni++) {
            int cb = bn + nBase + ni * 8 + 2 * col4;
            float2 b2 = make_float2(0.f, 0.f);
            if (bias) { b2.x = bias[cb]; b2.y = bias[cb + 1]; }

            float* p0 = C + (size_t)r0 * N + cb;
            float* p1 = C + (size_t)(r0 + 8) * N + cb;
            float2 v0 = make_float2(acc[mi][ni][0] + b2.x, acc[mi][ni][1] + b2.y);
            float2 v1 = make_float2(acc[mi][ni][2] + b2.x, acc[mi][ni][3] + b2.y);
            if (accFlag) {
                float2 o0 = *(float2*)p0, o1 = *(float2*)p1;
                v0.x += o0.x; v0.y += o0.y;
                v1.x += o1.x; v1.y += o1.y;
            }
            *(float2*)p0 = v0;
            *(float2*)p1 = v1;
        }
    }
}

// ---------------- residual add + RMSNorm (in-place into y2 buffer) ----------------
__global__ __launch_bounds__(256) void rmsnorm_kernel(
    float* __restrict__ y2, const float* __restrict__ x, const float* __restrict__ w)
{
    int m = blockIdx.x;
    float* yrow = y2 + (size_t)m * Hh;
    const float* xrow = x + (size_t)m * Hh;

    float ss = 0.f;
    for (int i = threadIdx.x; i < Hh; i += 256) {
        float t = yrow[i] + xrow[i];
        ss += t * t;
    }
#pragma unroll
    for (int off = 16; off > 0; off >>= 1)
        ss += __shfl_xor_sync(0xffffffffu, ss, off);

    __shared__ float red[9];
    int lane = threadIdx.x & 31, wid = threadIdx.x >> 5;
    if (lane == 0) red[wid] = ss;
    __syncthreads();
    if (threadIdx.x == 0) {
        float tot = 0.f;
        for (int i = 0; i < 8; i++) tot += red[i];
        red[8] = rsqrtf(tot / (float)Hh + EPSc);
    }
    __syncthreads();
    float inv = red[8];
    for (int i = threadIdx.x; i < Hh; i += 256) {
        float t = yrow[i] + xrow[i];
        yrow[i] = t * w[i] * inv;
    }
}

// ---------------- RoPE in place on qk buffer ----------------
__global__ __launch_bounds__(128) void rope_kernel(
    float* __restrict__ qkbuf, const float* __restrict__ freqs,
    const int* __restrict__ positions)
{
    int mh = blockIdx.x;
    int m = mh / NHh, h = mh % NHh;
    int pos = positions[m];
    int t = threadIdx.x;
    int isK = t >> 6;
    int d = t & 63;

    size_t base = (size_t)m * QKW + (size_t)h * 256 + (size_t)isK * 128;
    float f1 = freqs[(size_t)pos * HDd + d];
    float f2 = freqs[(size_t)pos * HDd + d + 64];
    float c1 = cosf(f1), s1 = sinf(f1);
    float c2 = cosf(f2), s2 = sinf(f2);
    float x1 = qkbuf[base + d];
    float x2 = qkbuf[base + d + 64];
    qkbuf[base + d]      = x1 * c1 - x2 * s1;
    qkbuf[base + d + 64] = x2 * c2 + x1 * s2;
}

// ---------------- causal flash attention ----------------
#define TQ 64
#define TK 32
__global__ __launch_bounds__(256) void flash_kernel(
    const float* __restrict__ qkbuf, const float* __restrict__ vbuf,
    float* __restrict__ attn)
{
    int qt = blockIdx.x;
    int h  = blockIdx.y;
    int b  = blockIdx.z;
    int q0 = qt * TQ;
    int tid = threadIdx.x;
    int g = tid >> 2;
    int part = tid & 3;

    __shared__ float Ks[TK][HDd];
    __shared__ float Vs[TK][HDd];

    int qi = q0 + g;
    size_t qbase = (size_t)(b * Ss + qi) * QKW + (size_t)h * 256;
    const float scale = 0.08838834764831845f;

    float qr[32], o[32];
#pragma unroll
    for (int i = 0; i < 32; i++) {
        qr[i] = qkbuf[qbase + i * 4 + part] * scale;
        o[i] = 0.f;
    }
    float mval = -1e30f, lval = 0.f;

    int kend = q0 + TQ;
    for (int j0 = 0; j0 < kend; j0 += TK) {
        __syncthreads();
        for (int t = tid; t < TK * HDd / 4; t += 256) {
            int row = t >> 5;
            int c4 = (t & 31) << 2;
            size_t kb = (size_t)(b * Ss + j0 + row) * QKW + (size_t)h * 256 + 128 + c4;
            size_t vb = (size_t)(b * Ss + j0 + row) * Pp + (size_t)h * HDd + c4;
            *(float4*)&Ks[row][c4] = *(const float4*)(qkbuf + kb);
            *(float4*)&Vs[row][c4] = *(const float4*)(vbuf + vb);
        }
        __syncthreads();

#pragma unroll 1
        for (int j = 0; j < TK; j++) {
            int kpos = j0 + j;
            float s = 0.f;
#pragma unroll
            for (int i = 0; i < 32; i++) s = fmaf(qr[i], Ks[j][i * 4 + part], s);
            s += __shfl_xor_sync(0xffffffffu, s, 1);
            s += __shfl_xor_sync(0xffffffffu, s, 2);
            if (kpos > qi) s = -1e30f;

            float mnew = fmaxf(mval, s);
            float alpha = __expf(mval - mnew);
            float p = __expf(s - mnew);
            lval = lval * alpha + p;
            mval = mnew;
#pragma unroll
            for (int i = 0; i < 32; i++)
                o[i] = fmaf(o[i], alpha, p * Vs[j][i * 4 + part]);
        }
    }

    float inv = 1.f / lval;
    size_t ob = (size_t)(b * Ss + qi) * Pp + (size_t)h * HDd;
#pragma unroll
    for (int i = 0; i < 32; i++) attn[ob + i * 4 + part] = o[i] * inv;
}

// ---------------- tail outputs ----------------
__global__ void tails_kernel(const float* __restrict__ hs, const float* __restrict__ y1,
                             float* __restrict__ out)
{
    int i = blockIdx.x * 256 + threadIdx.x;
    size_t off1 = (size_t)Mm * Hh;
    size_t off2 = off1 + (size_t)Bb * Hh;
    if (i < Bb * Hh) {
        int b = i / Hh, hh = i % Hh;
        out[off1 + i] = hs[((size_t)b * Ss + (Ss - 1)) * Hh + hh];
    }
    if (i < Bb * H2) {
        int b = i / H2, oo = i % H2;
        out[off2 + i] = y1[((size_t)b * Ss + (Ss - 1)) * H2 + oo];
    }
}

// ---------------- launch ----------------
extern "C" void kernel_launch(void* const* d_in, const int* in_sizes, int n_in,
                              void* d_out, int out_size)
{
    (void)in_sizes; (void)n_in; (void)out_size;
    const float* hs      = (const float*)d_in[0];
    const float* freqs   = (const float*)d_in[1];
    const int*   pos     = (const int*)  d_in[2];
    const float* Wqk     = (const float*)d_in[3];
    const float* Wv      = (const float*)d_in[4];
    const float* Wo      = (const float*)d_in[5];
    const float* conv1_w = (const float*)d_in[6];
    const float* conv1_b = (const float*)d_in[7];
    const float* conv2_w = (const float*)d_in[8];
    const float* conv2_b = (const float*)d_in[9];
    const float* ln_w    = (const float*)d_in[10];
    const float* lf1c    = (const float*)d_in[11];
    const float* lf2c    = (const float*)d_in[12];
    float* out = (float*)d_out;

    float *v, *xprev, *y1, *y1prev, *lfout, *qk, *attn;
    float *w1a, *w1b, *w2a, *w2b;
    cudaGetSymbolAddress((void**)&v,      g_v);
    cudaGetSymbolAddress((void**)&xprev,  g_xprev);
    cudaGetSymbolAddress((void**)&y1,     g_y1);
    cudaGetSymbolAddress((void**)&y1prev, g_y1prev);
    cudaGetSymbolAddress((void**)&lfout,  g_lfout);
    cudaGetSymbolAddress((void**)&qk,     g_qk);
    cudaGetSymbolAddress((void**)&attn,   g_attn);
    cudaGetSymbolAddress((void**)&w1a,    g_w1a);
    cudaGetSymbolAddress((void**)&w1b,    g_w1b);
    cudaGetSymbolAddress((void**)&w2a,    g_w2a);
    cudaGetSymbolAddress((void**)&w2b,    g_w2b);

    // 1) deinterleave conv weights
    {
        int n1 = H2 * Hh;
        deint_kernel<<<(n1 + 255) / 256, 256>>>(conv1_w, w1a, w1b, n1);
        int n2 = Hh * H2;
        deint_kernel<<<(n2 + 255) / 256, 256>>>(conv2_w, w2a, w2b, n2);
    }

    // 2) shifted hidden
    shift_kernel<<<Mm, 256>>>(hs, lf1c, xprev, Hh);

    // 3) v = hs @ Wv^T
    gemm_tf32_kernel<<<dim3(Pp / BNg, Mm / BMg), 256>>>(hs, Wv, v, Pp, Hh, nullptr, 0);

    // 4) y1 = xprev @ w1a^T + hs @ w1b^T + b1
    gemm_tf32_kernel<<<dim3(H2 / BNg, Mm / BMg), 256>>>(xprev, w1a, y1, H2, Hh, nullptr, 0);
    gemm_tf32_kernel<<<dim3(H2 / BNg, Mm / BMg), 256>>>(hs,    w1b, y1, H2, Hh, conv1_b, 1);

    // 5) shifted y1
    shift_kernel<<<Mm, 256>>>(y1, lf2c, y1prev, H2);

    // 6) y2 = y1prev @ w2a^T + y1 @ w2b^T + b2
    gemm_tf32_kernel<<<dim3(Hh / BNg, Mm / BMg), 256>>>(y1prev, w2a, lfout, Hh, H2, nullptr, 0);
    gemm_tf32_kernel<<<dim3(Hh / BNg, Mm / BMg), 256>>>(y1,     w2b, lfout, Hh, H2, conv2_b, 1);

    // 7) lf_out = rmsnorm(y2 + hs) * ln_w
    rmsnorm_kernel<<<Mm, 256>>>(lfout, hs, ln_w);

    // 8) qk = lf_out @ Wqk^T
    gemm_tf32_kernel<<<dim3(QKW / BNg, Mm / BMg), 256>>>(lfout, Wqk, qk, QKW, Hh, nullptr, 0);

    // 9) RoPE in place
    rope_kernel<<<Mm * NHh, 128>>>(qk, freqs, pos);

    // 10) causal flash attention
    flash_kernel<<<dim3(Ss / TQ, NHh, Bb), 256>>>(qk, v, attn);

    // 11) output = attn @ Wo^T
    gemm_tf32_kernel<<<dim3(Hh / BNg, Mm / BMg), 256>>>(attn, Wo, out, Hh, Pp, nullptr, 0);

    // 12) tails
    tails_kernel<<<(Bb * Hh + 255) / 256, 256>>>(hs, y1, out);
}

// round 4
// speedup vs baseline: 1.8611x; 1.0163x over previous
#include <cuda_runtime.h>
#include <cuda_bf16.h>
#include <cstdint>
#include <cstddef>

// Problem constants
#define Bb   2
#define Ss   2048
#define Hh   2048
#define NHh  16
#define HDd  128
#define Pp   2048
#define Mm   (Bb * Ss)          // 4096 rows
#define H2   (Hh / 2)           // 1024
#define QKW  (2 * Pp)           // 4096 (qk row width)
#define EPSc 1e-6f

// ---------------- scratch (static device globals; no allocation) ----------------
__device__ float g_v[(size_t)Mm * Pp];
__device__ float g_xprev[(size_t)Mm * Hh];
__device__ float g_y1[(size_t)Mm * H2];
__device__ float g_y1prev[(size_t)Mm * H2];
__device__ float g_lfout[(size_t)Mm * Hh];
__device__ float g_qk[(size_t)Mm * QKW];
__device__ float g_attn[(size_t)Mm * Pp];
__device__ float g_w1a[(size_t)H2 * Hh];
__device__ float g_w1b[(size_t)H2 * Hh];
__device__ float g_w2a[(size_t)Hh * H2];
__device__ float g_w2b[(size_t)Hh * H2];

// ---------------- helpers ----------------
__device__ __forceinline__ uint32_t f2tf(float x) {
    uint32_t r;
    asm("cvt.rna.tf32.f32 %0, %1;" : "=r"(r) : "f"(x));
    return r;
}

__device__ __forceinline__ void mma_tf32(float* d, const uint32_t* a, const uint32_t* b) {
    asm volatile(
        "mma.sync.aligned.m16n8k8.row.col.f32.tf32.tf32.f32 "
        "{%0,%1,%2,%3},{%4,%5,%6,%7},{%8,%9},{%0,%1,%2,%3};"
        : "+f"(d[0]), "+f"(d[1]), "+f"(d[2]), "+f"(d[3])
        : "r"(a[0]), "r"(a[1]), "r"(a[2]), "r"(a[3]), "r"(b[0]), "r"(b[1]));
}

__device__ __forceinline__ void cp16(void* smem, const void* g) {
    uint32_t s = (uint32_t)__cvta_generic_to_shared(smem);
    asm volatile("cp.async.ca.shared.global [%0], [%1], 16;" :: "r"(s), "l"(g));
}

// ---------------- deinterleave conv weights ----------------
__global__ void deint_kernel(const float* __restrict__ in, float* __restrict__ a,
                             float* __restrict__ b, int n)
{
    int i = blockIdx.x * 256 + threadIdx.x;
    if (i < n) {
        a[i] = in[2 * i];
        b[i] = in[2 * i + 1];
    }
}

// ---------------- shift rows by one seq step ----------------
__global__ void shift_kernel(const float* __restrict__ x, const float* __restrict__ cache,
                             float* __restrict__ out, int width)
{
    int m = blockIdx.x;
    int s = m % Ss;
    int b = m / Ss;
    const float* src = (s == 0) ? (cache + (size_t)b * width)
                                : (x + (size_t)(m - 1) * width);
    float* dst = out + (size_t)m * width;
    for (int i = threadIdx.x; i < width; i += 256) dst[i] = src[i];
}

// ---------------- TF32 tensor-core GEMM (NT): C[M,N] = A[M,K] * W[N,K]^T (+bias)(+C) ----------------
// 128x128 block tile, BK=16, 256 threads = 8 warps (2x4), warp tile 64x32 via m16n8k8.
// All dims % 128 == 0, K % 16 == 0.
#define BMg 128
#define BNg 128
#define BKg 16
#define PADg 20   // floats per smem row (keeps 16B align, conflict-free frags)

__global__ __launch_bounds__(256) void gemm_tf32_kernel(
    const float* __restrict__ A, const float* __restrict__ W, float* __restrict__ C,
    int N, int K, const float* __restrict__ bias, int accFlag)
{
    __shared__ float As[2][BMg * PADg];
    __shared__ float Bs[2][BNg * PADg];

    const int tid = threadIdx.x;
    const int lane = tid & 31;
    const int warp = tid >> 5;
    const int wm = warp >> 2;          // 0..1
    const int wn = warp & 3;           // 0..3
    const int bm = blockIdx.y * BMg;
    const int bn = blockIdx.x * BNg;
    const int mBase = wm * 64;
    const int nBase = wn * 32;

    float acc[4][4][4];
#pragma unroll
    for (int mi = 0; mi < 4; mi++)
#pragma unroll
        for (int ni = 0; ni < 4; ni++)
#pragma unroll
            for (int e = 0; e < 4; e++) acc[mi][ni][e] = 0.f;

    const int nk = K / BKg;

    // chunk c in [0,512): row = c>>2, col floats = (c&3)*4 ; thread does c=tid, tid+256
    auto load_tiles = [&](int buf, int k0) {
#pragma unroll
        for (int c = tid; c < 512; c += 256) {
            int row = c >> 2;
            int colf = (c & 3) << 2;
            cp16(&As[buf][row * PADg + colf], A + (size_t)(bm + row) * K + k0 + colf);
            cp16(&Bs[buf][row * PADg + colf], W + (size_t)(bn + row) * K + k0 + colf);
        }
        asm volatile("cp.async.commit_group;");
    };

    load_tiles(0, 0);

    const int row4 = lane >> 2;   // 0..7
    const int col4 = lane & 3;    // 0..3

    for (int kt = 0; kt < nk; kt++) {
        int buf = kt & 1;
        if (kt + 1 < nk) {
            load_tiles(buf ^ 1, (kt + 1) * BKg);
            asm volatile("cp.async.wait_group 1;");
        } else {
            asm volatile("cp.async.wait_group 0;");
        }
        __syncthreads();

        const float* as = &As[buf][0];
        const float* bs = &Bs[buf][0];
#pragma unroll
        for (int kk = 0; kk < BKg; kk += 8) {
            uint32_t af[4][4], bf[4][2];
#pragma unroll
            for (int mi = 0; mi < 4; mi++) {
                int m0 = mBase + mi * 16;
                af[mi][0] = f2tf(as[(m0 + row4) * PADg + kk + col4]);
                af[mi][1] = f2tf(as[(m0 + row4 + 8) * PADg + kk + col4]);
                af[mi][2] = f2tf(as[(m0 + row4) * PADg + kk + col4 + 4]);
                af[mi][3] = f2tf(as[(m0 + row4 + 8) * PADg + kk + col4 + 4]);
            }
#pragma unroll
            for (int ni = 0; ni < 4; ni++) {
                int n0 = nBase + ni * 8;
                bf[ni][0] = f2tf(bs[(n0 + row4) * PADg + kk + col4]);
                bf[ni][1] = f2tf(bs[(n0 + row4) * PADg + kk + col4 + 4]);
            }
#pragma unroll
            for (int mi = 0; mi < 4; mi++)
#pragma unroll
                for (int ni = 0; ni < 4; ni++)
                    mma_tf32(acc[mi][ni], af[mi], bf[ni]);
        }
        __syncthreads();
    }

    // epilogue: c0,c1 at (row4, 2*col4+{0,1}); c2,c3 at (row4+8, same)
#pragma unroll
    for (int mi = 0; mi < 4; mi++) {
        int r0 = bm + mBase + mi * 16 + row4;
#pragma unroll
        for (int ni = 0; ni < 4; ni++) {
            int cb = bn + nBase + ni * 8 + 2 * col4;
            float2 b2 = make_float2(0.f, 0.f);
            if (bias) { b2.x = bias[cb]; b2.y = bias[cb + 1]; }

            float* p0 = C + (size_t)r0 * N + cb;
            float* p1 = C + (size_t)(r0 + 8) * N + cb;
            float2 v0 = make_float2(acc[mi][ni][0] + b2.x, acc[mi][ni][1] + b2.y);
            float2 v1 = make_float2(acc[mi][ni][2] + b2.x, acc[mi][ni][3] + b2.y);
            if (accFlag) {
                float2 o0 = *(float2*)p0, o1 = *(float2*)p1;
                v0.x += o0.x; v0.y += o0.y;
                v1.x += o1.x; v1.y += o1.y;
            }
            *(float2*)p0 = v0;
            *(float2*)p1 = v1;
        }
    }
}

// ---------------- residual add + RMSNorm (in-place into y2 buffer) ----------------
__global__ __launch_bounds__(256) void rmsnorm_kernel(
    float* __restrict__ y2, const float* __restrict__ x, const float* __restrict__ w)
{
    int m = blockIdx.x;
    float* yrow = y2 + (size_t)m * Hh;
    const float* xrow = x + (size_t)m * Hh;

    float ss = 0.f;
    for (int i = threadIdx.x; i < Hh; i += 256) {
        float t = yrow[i] + xrow[i];
        ss += t * t;
    }
#pragma unroll
    for (int off = 16; off > 0; off >>= 1)
        ss += __shfl_xor_sync(0xffffffffu, ss, off);

    __shared__ float red[9];
    int lane = threadIdx.x & 31, wid = threadIdx.x >> 5;
    if (lane == 0) red[wid] = ss;
    __syncthreads();
    if (threadIdx.x == 0) {
        float tot = 0.f;
        for (int i = 0; i < 8; i++) tot += red[i];
        red[8] = rsqrtf(tot / (float)Hh + EPSc);
    }
    __syncthreads();
    float inv = red[8];
    for (int i = threadIdx.x; i < Hh; i += 256) {
        float t = yrow[i] + xrow[i];
        yrow[i] = t * w[i] * inv;
    }
}

// ---------------- RoPE in place on qk buffer ----------------
__global__ __launch_bounds__(128) void rope_kernel(
    float* __restrict__ qkbuf, const float* __restrict__ freqs,
    const int* __restrict__ positions)
{
    int mh = blockIdx.x;
    int m = mh / NHh, h = mh % NHh;
    int pos = positions[m];
    int t = threadIdx.x;
    int isK = t >> 6;
    int d = t & 63;

    size_t base = (size_t)m * QKW + (size_t)h * 256 + (size_t)isK * 128;
    float f1 = freqs[(size_t)pos * HDd + d];
    float f2 = freqs[(size_t)pos * HDd + d + 64];
    float c1 = cosf(f1), s1 = sinf(f1);
    float c2 = cosf(f2), s2 = sinf(f2);
    float x1 = qkbuf[base + d];
    float x2 = qkbuf[base + d + 64];
    qkbuf[base + d]      = x1 * c1 - x2 * s1;
    qkbuf[base + d + 64] = x2 * c2 + x1 * s2;
}

// ---------------- causal flash attention ----------------
#define TQ 64
#define TK 32
__global__ __launch_bounds__(256) void flash_kernel(
    const float* __restrict__ qkbuf, const float* __restrict__ vbuf,
    float* __restrict__ attn)
{
    int qt = blockIdx.x;
    int h  = blockIdx.y;
    int b  = blockIdx.z;
    int q0 = qt * TQ;
    int tid = threadIdx.x;
    int g = tid >> 2;
    int part = tid & 3;

    __shared__ float Ks[TK][HDd];
    __shared__ float Vs[TK][HDd];

    int qi = q0 + g;
    size_t qbase = (size_t)(b * Ss + qi) * QKW + (size_t)h * 256;
    const float scale = 0.08838834764831845f;

    float qr[32], o[32];
#pragma unroll
    for (int i = 0; i < 32; i++) {
        qr[i] = qkbuf[qbase + i * 4 + part] * scale;
        o[i] = 0.f;
    }
    float mval = -1e30f, lval = 0.f;

    int kend = q0 + TQ;
    for (int j0 = 0; j0 < kend; j0 += TK) {
        __syncthreads();
        for (int t = tid; t < TK * HDd / 4; t += 256) {
            int row = t >> 5;
            int c4 = (t & 31) << 2;
            size_t kb = (size_t)(b * Ss + j0 + row) * QKW + (size_t)h * 256 + 128 + c4;
            size_t vb = (size_t)(b * Ss + j0 + row) * Pp + (size_t)h * HDd + c4;
            *(float4*)&Ks[row][c4] = *(const float4*)(qkbuf + kb);
            *(float4*)&Vs[row][c4] = *(const float4*)(vbuf + vb);
        }
        __syncthreads();

#pragma unroll 1
        for (int j = 0; j < TK; j++) {
            int kpos = j0 + j;
            float s = 0.f;
#pragma unroll
            for (int i = 0; i < 32; i++) s = fmaf(qr[i], Ks[j][i * 4 + part], s);
            s += __shfl_xor_sync(0xffffffffu, s, 1);
            s += __shfl_xor_sync(0xffffffffu, s, 2);
            if (kpos > qi) s = -1e30f;

            float mnew = fmaxf(mval, s);
            float alpha = __expf(mval - mnew);
            float p = __expf(s - mnew);
            lval = lval * alpha + p;
            mval = mnew;
#pragma unroll
            for (int i = 0; i < 32; i++)
                o[i] = fmaf(o[i], alpha, p * Vs[j][i * 4 + part]);
        }
    }

    float inv = 1.f / lval;
    size_t ob = (size_t)(b * Ss + qi) * Pp + (size_t)h * HDd;
#pragma unroll
    for (int i = 0; i < 32; i++) attn[ob + i * 4 + part] = o[i] * inv;
}

// ---------------- tail outputs ----------------
__global__ void tails_kernel(const float* __restrict__ hs, const float* __restrict__ y1,
                             float* __restrict__ out)
{
    int i = blockIdx.x * 256 + threadIdx.x;
    size_t off1 = (size_t)Mm * Hh;
    size_t off2 = off1 + (size_t)Bb * Hh;
    if (i < Bb * Hh) {
        int b = i / Hh, hh = i % Hh;
        out[off1 + i] = hs[((size_t)b * Ss + (Ss - 1)) * Hh + hh];
    }
    if (i < Bb * H2) {
        int b = i / H2, oo = i % H2;
        out[off2 + i] = y1[((size_t)b * Ss + (Ss - 1)) * H2 + oo];
    }
}

// ---------------- launch ----------------
extern "C" void kernel_launch(void* const* d_in, const int* in_sizes, int n_in,
                              void* d_out, int out_size)
{
    (void)in_sizes; (void)n_in; (void)out_size;
    const float* hs      = (const float*)d_in[0];
    const float* freqs   = (const float*)d_in[1];
    const int*   pos     = (const int*)  d_in[2];
    const float* Wqk     = (const float*)d_in[3];
    const float* Wv      = (const float*)d_in[4];
    const float* Wo      = (const float*)d_in[5];
    const float* conv1_w = (const float*)d_in[6];
    const float* conv1_b = (const float*)d_in[7];
    const float* conv2_w = (const float*)d_in[8];
    const float* conv2_b = (const float*)d_in[9];
    const float* ln_w    = (const float*)d_in[10];
    const float* lf1c    = (const float*)d_in[11];
    const float* lf2c    = (const float*)d_in[12];
    float* out = (float*)d_out;

    float *v, *xprev, *y1, *y1prev, *lfout, *qk, *attn;
    float *w1a, *w1b, *w2a, *w2b;
    cudaGetSymbolAddress((void**)&v,      g_v);
    cudaGetSymbolAddress((void**)&xprev,  g_xprev);
    cudaGetSymbolAddress((void**)&y1,     g_y1);
    cudaGetSymbolAddress((void**)&y1prev, g_y1prev);
    cudaGetSymbolAddress((void**)&lfout,  g_lfout);
    cudaGetSymbolAddress((void**)&qk,     g_qk);
    cudaGetSymbolAddress((void**)&attn,   g_attn);
    cudaGetSymbolAddress((void**)&w1a,    g_w1a);
    cudaGetSymbolAddress((void**)&w1b,    g_w1b);
    cudaGetSymbolAddress((void**)&w2a,    g_w2a);
    cudaGetSymbolAddress((void**)&w2b,    g_w2b);

    // 1) deinterleave conv weights
    {
        int n1 = H2 * Hh;
        deint_kernel<<<(n1 + 255) / 256, 256>>>(conv1_w, w1a, w1b, n1);
        int n2 = Hh * H2;
        deint_kernel<<<(n2 + 255) / 256, 256>>>(conv2_w, w2a, w2b, n2);
    }

    // 2) shifted hidden
    shift_kernel<<<Mm, 256>>>(hs, lf1c, xprev, Hh);

    // 3) v = hs @ Wv^T
    gemm_tf32_kernel<<<dim3(Pp / BNg, Mm / BMg), 256>>>(hs, Wv, v, Pp, Hh, nullptr, 0);

    // 4) y1 = xprev @ w1a^T + hs @ w1b^T + b1
    gemm_tf32_kernel<<<dim3(H2 / BNg, Mm / BMg), 256>>>(xprev, w1a, y1, H2, Hh, nullptr, 0);
    gemm_tf32_kernel<<<dim3(H2 / BNg, Mm / BMg), 256>>>(hs,    w1b, y1, H2, Hh, conv1_b, 1);

    // 5) shifted y1
    shift_kernel<<<Mm, 256>>>(y1, lf2c, y1prev, H2);

    // 6) y2 = y1prev @ w2a^T + y1 @ w2b^T + b2
    gemm_tf32_kernel<<<dim3(Hh / BNg, Mm / BMg), 256>>>(y1prev, w2a, lfout, Hh, H2, nullptr, 0);
    gemm_tf32_kernel<<<dim3(Hh / BNg, Mm / BMg), 256>>>(y1,     w2b, lfout, Hh, H2, conv2_b, 1);

    // 7) lf_out = rmsnorm(y2 + hs) * ln_w
    rmsnorm_kernel<<<Mm, 256>>>(lfout, hs, ln_w);

    // 8) qk = lf_out @ Wqk^T
    gemm_tf32_kernel<<<dim3(QKW / BNg, Mm / BMg), 256>>>(lfout, Wqk, qk, QKW, Hh, nullptr, 0);

    // 9) RoPE in place
    rope_kernel<<<Mm * NHh, 128>>>(qk, freqs, pos);

    // 10) causal flash attention
    flash_kernel<<<dim3(Ss / TQ, NHh, Bb), 256>>>(qk, v, attn);

    // 11) output = attn @ Wo^T
    gemm_tf32_kernel<<<dim3(Hh / BNg, Mm / BMg), 256>>>(attn, Wo, out, Hh, Pp, nullptr, 0);

    // 12) tails
    tails_kernel<<<(Bb * Hh + 255) / 256, 256>>>(hs, y1, out);
}